// round 9
// baseline (speedup 1.0000x reference)
#include <cuda_runtime.h>
#include <cuda_bf16.h>
#include <cstdint>

// Problem: S=128, I=J=512, CM=256, C=D=32, CZ=128
// opm CTA = 4i x 8j pairs; grid (64 jt, 128 it); 512 threads.
// Phase A: D[128m x 256n], K=384 (bf16 3-term split). 16 warps, tile 32x64.
// Phase B: Z[128cz x 32p], K=16kt x 3terms x 64k.
//   2 groups (kt parity) x 4 cz-tiles x 2 k16-halves; double-buffered 32-k Wo stages.

// ---------------- smem layout (bytes) ----------------
#define ABUF(b)   ((b) * 55296)
#define BOFF      18432
#define OHI       0
#define OLO       66048
#define OSTRIDE   2064
#define WO_OFF    132096
#define GBUF_SZ   40960     // per group: 2 stages x (hi 10240 + lo 10240)
#define STG_SZ    20480
#define WSTR      80        // Wo stage row stride (64B data + 16 pad)
#define TSTRIDE   144
#define SMEM2     214016
#define K1_SMEM   ((2*32*260 + 16*256) * 4)

// Pre-tiled globals (plain [row][64k] bf16 tiles):
__device__ __align__(256) __nv_bfloat16 g_A3[128 * 6 * 8192];
__device__ __align__(256) __nv_bfloat16 g_B3[64 * 6 * 16384];
__device__ __align__(256) __nv_bfloat16 g_Wo3[32 * 8192];   // kt0-15 hi, 16-31 lo

// ---------------- helpers ----------------
__device__ __forceinline__ uint32_t smem_u32(const void* p) {
    uint32_t a;
    asm("{ .reg .u64 t; cvta.to.shared.u64 t, %1; cvt.u32.u64 %0, t; }" : "=r"(a) : "l"(p));
    return a;
}
__device__ __forceinline__ void cp16(uint32_t smdst, const void* src) {
    asm volatile("cp.async.cg.shared.global [%0], [%1], 16;" :: "r"(smdst), "l"(src));
}
__device__ __forceinline__ void cp_commit() { asm volatile("cp.async.commit_group;"); }
template<int N> __device__ __forceinline__ void cp_wait() {
    asm volatile("cp.async.wait_group %0;" :: "n"(N));
}
__device__ __forceinline__ void barx(int id) {
    asm volatile("bar.sync %0, 256;" :: "r"(id) : "memory");
}
__device__ __forceinline__ void ldm_x4(uint32_t* r, uint32_t addr) {
    asm volatile("ldmatrix.sync.aligned.m8n8.x4.shared.b16 {%0,%1,%2,%3}, [%4];"
                 : "=r"(r[0]), "=r"(r[1]), "=r"(r[2]), "=r"(r[3]) : "r"(addr));
}
__device__ __forceinline__ void mma16816(float* d, const uint32_t* a, uint32_t b0, uint32_t b1) {
    asm volatile(
        "mma.sync.aligned.m16n8k16.row.col.f32.bf16.bf16.f32 "
        "{%0,%1,%2,%3}, {%4,%5,%6,%7}, {%8,%9}, {%0,%1,%2,%3};"
        : "+f"(d[0]), "+f"(d[1]), "+f"(d[2]), "+f"(d[3])
        : "r"(a[0]), "r"(a[1]), "r"(a[2]), "r"(a[3]), "r"(b0), "r"(b1));
}
__device__ __forceinline__ uint32_t packbf(float lo, float hi) {  // lo -> low half
    uint32_t r;
    asm("cvt.rn.satfinite.bf16x2.f32 %0, %1, %2;" : "=r"(r) : "f"(hi), "f"(lo));
    return r;
}
// stage contiguous [rows][64] bf16 tile into smem (TSTRIDE-padded rows)
__device__ __forceinline__ void stage_tile(uint32_t smdst, const __nv_bfloat16* g,
                                           int rows, int t, int nthr) {
    const char* s = (const char*)g;
    for (int idx = t; idx < rows * 8; idx += nthr) {
        int r = idx >> 3, c = idx & 7;
        cp16(smdst + r * TSTRIDE + c * 16, s + r * 128 + c * 16);
    }
}
// stage one 32-k Wo stage (hi+lo halves of tile kt, k-half khalf) with 256 threads
__device__ __forceinline__ void stage_w(uint32_t dst, int kt, int khalf, int gt) {
    const char* hi = (const char*)(g_Wo3 + (size_t)kt * 8192) + khalf * 64;
    const char* lo = (const char*)(g_Wo3 + (size_t)(16 + kt) * 8192) + khalf * 64;
    #pragma unroll
    for (int idx = gt; idx < 512; idx += 256) {
        int r = idx >> 2, c = idx & 3;
        cp16(dst + r * WSTR + c * 16,         hi + r * 128 + c * 16);
        cp16(dst + 10240 + r * WSTR + c * 16, lo + r * 128 + c * 16);
    }
}

// =====================================================================
// Kernel 0: split Wo into hi/lo tiled global.
// =====================================================================
__global__ void wo_prep_kernel(const float* __restrict__ Wo) {
    int idx = blockIdx.x * 256 + threadIdx.x;      // 131072
    int cz = idx >> 10, k = idx & 1023;
    int kt = k >> 6, kk = k & 63;
    float w = Wo[idx];
    __nv_bfloat16 h = __float2bfloat16(w);
    __nv_bfloat16 l = __float2bfloat16(w - __bfloat162float(h));
    g_Wo3[kt * 8192 + cz * 64 + kk]        = h;
    g_Wo3[(16 + kt) * 8192 + cz * 64 + kk] = l;
}

// =====================================================================
// Kernel 1: LayerNorm + dual projection (2 rows per warp -> weight reuse).
// =====================================================================
__global__ __launch_bounds__(256, 2)
void ln_proj_kernel(const float* __restrict__ x,
                    const float* __restrict__ nw,
                    const float* __restrict__ nb,
                    const float* __restrict__ Wa,
                    const float* __restrict__ Wb)
{
    extern __shared__ float sm[];
    float* Wa_s = sm;                 // [32][260]
    float* Wb_s = sm + 32 * 260;
    float* ln_s = sm + 2 * 32 * 260;  // [16][256]

    const int t = threadIdx.x, lane = t & 31, w = t >> 5;

    for (int idx = t; idx < 8192; idx += 256) {
        int c = idx >> 8, m = idx & 255;
        Wa_s[c * 260 + m] = Wa[idx];
        Wb_s[c * 260 + m] = Wb[idx];
    }

    const int r0 = blockIdx.x * 16 + w * 2;
    #pragma unroll
    for (int rr = 0; rr < 2; rr++) {
        const int row = r0 + rr;
        const float* xr = x + (size_t)row * 256;
        float v[8]; float s = 0.f, sq = 0.f;
        #pragma unroll
        for (int h = 0; h < 2; h++) {
            float4 x4 = *(const float4*)(xr + lane * 4 + 128 * h);
            v[h*4+0]=x4.x; v[h*4+1]=x4.y; v[h*4+2]=x4.z; v[h*4+3]=x4.w;
            s  += x4.x + x4.y + x4.z + x4.w;
            sq += x4.x*x4.x + x4.y*x4.y + x4.z*x4.z + x4.w*x4.w;
        }
        #pragma unroll
        for (int o = 16; o > 0; o >>= 1) {
            s  += __shfl_xor_sync(0xffffffffu, s,  o);
            sq += __shfl_xor_sync(0xffffffffu, sq, o);
        }
        float mu  = s * (1.f / 256.f);
        float var = sq * (1.f / 256.f) - mu * mu;
        float rs  = rsqrtf(var + 1e-5f);
        #pragma unroll
        for (int h = 0; h < 2; h++) {
            int m0 = lane * 4 + 128 * h;
            float4 w4 = *(const float4*)(nw + m0);
            float4 b4 = *(const float4*)(nb + m0);
            float* lp = ln_s + (w * 2 + rr) * 256 + m0;
            lp[0] = (v[h*4+0]-mu)*rs*w4.x + b4.x;
            lp[1] = (v[h*4+1]-mu)*rs*w4.y + b4.y;
            lp[2] = (v[h*4+2]-mu)*rs*w4.z + b4.z;
            lp[3] = (v[h*4+3]-mu)*rs*w4.w + b4.w;
        }
    }
    __syncthreads();

    float accA[2] = {0.f, 0.f}, accB[2] = {0.f, 0.f};
    const float* lr0 = ln_s + (w * 2) * 256;
    const float* lr1 = lr0 + 256;
    const float* war = Wa_s + lane * 260;
    const float* wbr = Wb_s + lane * 260;
    #pragma unroll 8
    for (int m4 = 0; m4 < 64; m4++) {
        float4 wa4 = *(const float4*)(war + m4 * 4);
        float4 wb4 = *(const float4*)(wbr + m4 * 4);
        float4 l0  = *(const float4*)(lr0 + m4 * 4);
        float4 l1  = *(const float4*)(lr1 + m4 * 4);
        accA[0] = fmaf(l0.x, wa4.x, accA[0]); accA[0] = fmaf(l0.y, wa4.y, accA[0]);
        accA[0] = fmaf(l0.z, wa4.z, accA[0]); accA[0] = fmaf(l0.w, wa4.w, accA[0]);
        accB[0] = fmaf(l0.x, wb4.x, accB[0]); accB[0] = fmaf(l0.y, wb4.y, accB[0]);
        accB[0] = fmaf(l0.z, wb4.z, accB[0]); accB[0] = fmaf(l0.w, wb4.w, accB[0]);
        accA[1] = fmaf(l1.x, wa4.x, accA[1]); accA[1] = fmaf(l1.y, wa4.y, accA[1]);
        accA[1] = fmaf(l1.z, wa4.z, accA[1]); accA[1] = fmaf(l1.w, wa4.w, accA[1]);
        accB[1] = fmaf(l1.x, wb4.x, accB[1]); accB[1] = fmaf(l1.y, wb4.y, accB[1]);
        accB[1] = fmaf(l1.z, wb4.z, accB[1]); accB[1] = fmaf(l1.w, wb4.w, accB[1]);
    }

    #pragma unroll
    for (int rr = 0; rr < 2; rr++) {
        const int row = r0 + rr;
        __nv_bfloat16 ah = __float2bfloat16(accA[rr]);
        __nv_bfloat16 al = __float2bfloat16(accA[rr] - __bfloat162float(ah));
        __nv_bfloat16 bh = __float2bfloat16(accB[rr]);
        __nv_bfloat16 bl = __float2bfloat16(accB[rr] - __bfloat162float(bh));
        const int ss = row >> 9, ij = row & 511;
        const int kts = ss >> 6, kk = ss & 63;
        {   // A terms: kt = kts(ahi), 2+kts(ahi), 4+kts(alo)
            int it = ij >> 2, m = (ij & 3) * 32 + lane;
            __nv_bfloat16* base = g_A3 + (size_t)(it * 6) * 8192 + m * 64 + kk;
            base[(size_t)kts * 8192]       = ah;
            base[(size_t)(2 + kts) * 8192] = ah;
            base[(size_t)(4 + kts) * 8192] = al;
        }
        {   // B terms: bhi, blo, bhi
            int jt = ij >> 3, n = (ij & 7) * 32 + lane;
            __nv_bfloat16* base = g_B3 + (size_t)(jt * 6) * 16384 + n * 64 + kk;
            base[(size_t)kts * 16384]       = bh;
            base[(size_t)(2 + kts) * 16384] = bl;
            base[(size_t)(4 + kts) * 16384] = bh;
        }
    }
}

// =====================================================================
// Kernel 2: fused OPM + projection, 512 threads.
// =====================================================================
__global__ __launch_bounds__(512, 1)
void opm_kernel(const float* __restrict__ bo, float* __restrict__ out)
{
    extern __shared__ char smc[];
    const uint32_t sb = smem_u32(smc);
    const int t = threadIdx.x, lane = t & 31, wid = t >> 5;
    const int jt = blockIdx.x, it = blockIdx.y;
    const int g  = wid >> 3;              // phase-B group (kt parity)
    const int gt = t & 255;

    const __nv_bfloat16* Abase = g_A3 + (size_t)(it * 6) * 8192;
    const __nv_bfloat16* Bbase = g_B3 + (size_t)(jt * 6) * 16384;

    // ---- prologue. Per-thread commits: c0=AB0 c1=AB1 c2=Wstage0 c3=Wstage1 ----
    stage_tile(sb + ABUF(0),        Abase,         128, t, 512);
    stage_tile(sb + ABUF(0) + BOFF, Bbase,         256, t, 512);
    cp_commit();                                                    // c0
    stage_tile(sb + ABUF(1),        Abase + 8192,  128, t, 512);
    stage_tile(sb + ABUF(1) + BOFF, Bbase + 16384, 256, t, 512);
    cp_commit();                                                    // c1
    {   // group g: stage0 = (kt=g, k0-31), stage1 = (kt=g, k32-63)
        uint32_t WB = sb + WO_OFF + g * GBUF_SZ;
        stage_w(WB,          g, 0, gt);  cp_commit();               // c2
        stage_w(WB + STG_SZ, g, 1, gt);  cp_commit();               // c3
    }

    // ---- Phase A: 16 warps, 4x4 grid of 32m x 64n tiles ----
    const int wm = wid & 3, wn = wid >> 2;
    const uint32_t lrow = (uint32_t)(lane & 15) * TSTRIDE;
    const uint32_t lcol = (uint32_t)(lane >> 4) * 16;
    float acc[2][8][4];
    #pragma unroll
    for (int mt = 0; mt < 2; mt++)
        #pragma unroll
        for (int nt = 0; nt < 8; nt++)
            #pragma unroll
            for (int e = 0; e < 4; e++) acc[mt][nt][e] = 0.f;

    #pragma unroll 1
    for (int kt = 0; kt < 6; kt++) {
        // commits audited: kt<2: wait<3>; 2..4: wait<1>; 5: wait<0>
        if (kt < 2) cp_wait<3>(); else if (kt < 5) cp_wait<1>(); else cp_wait<0>();
        __syncthreads();
        const uint32_t ab = sb + ABUF(kt & 1);
        const uint32_t aB = ab + (uint32_t)(wm * 32) * TSTRIDE + lrow + lcol;
        const uint32_t bB = ab + BOFF + (uint32_t)(wn * 64) * TSTRIDE + lrow + lcol;
        #pragma unroll
        for (int k16 = 0; k16 < 4; k16++) {
            uint32_t A4[2][4], B4[4][4];
            #pragma unroll
            for (int mt = 0; mt < 2; mt++) ldm_x4(A4[mt], aB + mt * 16 * TSTRIDE + k16 * 32);
            #pragma unroll
            for (int bt = 0; bt < 4; bt++) ldm_x4(B4[bt], bB + bt * 16 * TSTRIDE + k16 * 32);
            #pragma unroll
            for (int mt = 0; mt < 2; mt++)
                #pragma unroll
                for (int bt = 0; bt < 4; bt++) {
                    mma16816(acc[mt][bt*2],   A4[mt], B4[bt][0], B4[bt][2]);
                    mma16816(acc[mt][bt*2+1], A4[mt], B4[bt][1], B4[bt][3]);
                }
        }
        __syncthreads();
        if (kt < 4) {
            stage_tile(sb + ABUF(kt & 1),        Abase + (size_t)(kt+2) * 8192,  128, t, 512);
            stage_tile(sb + ABUF(kt & 1) + BOFF, Bbase + (size_t)(kt+2) * 16384, 256, t, 512);
            cp_commit();                                            // c4..c7
        }
    }

    // ---- Epilogue: accums -> O hi/lo smem (swizzled cols: 2-way conflicts) ----
    {
        const int m0 = wm * 32, n0 = wn * 64;
        const int mr = lane >> 2, nc = (lane & 3) * 2;
        #pragma unroll
        for (int mt = 0; mt < 2; mt++)
            #pragma unroll
            for (int nt = 0; nt < 8; nt++) {
                #pragma unroll
                for (int h = 0; h < 2; h++) {
                    int m = m0 + mt * 16 + mr + h * 8;
                    int n = n0 + nt * 8 + nc;
                    float f0 = acc[mt][nt][2*h]   * (1.f / 128.f);
                    float f1 = acc[mt][nt][2*h+1] * (1.f / 128.f);
                    float h0 = __bfloat162float(__float2bfloat16(f0));
                    float h1 = __bfloat162float(__float2bfloat16(f1));
                    uint32_t hi = packbf(f0, f1);
                    uint32_t lo = packbf(f0 - h0, f1 - h1);
                    int p = (m >> 5) * 8 + (n >> 5);
                    uint32_t col = (uint32_t)(((m & 31) * 32 + (n & 31)) * 2);
                    col ^= ((col >> 6) & 3) << 4;
                    uint32_t off = (uint32_t)(p * OSTRIDE) + col;
                    asm volatile("st.shared.b32 [%0], %1;" :: "r"(sb + OHI + off), "r"(hi) : "memory");
                    asm volatile("st.shared.b32 [%0], %1;" :: "r"(sb + OLO + off), "r"(lo) : "memory");
                }
            }
    }
    __syncthreads();

    // ---- Phase B: warp (g, ct, kh); stages q=0..15: kt=g+2*(q>>1), k-half q&1 ----
    float z[2][4][4];
    #pragma unroll
    for (int hf = 0; hf < 2; hf++)
        #pragma unroll
        for (int ni = 0; ni < 4; ni++)
            #pragma unroll
            for (int e = 0; e < 4; e++) z[hf][ni][e] = 0.f;

    const int wg = wid & 7, ct = wg >> 1, kh = wg & 1;
    const uint32_t WB   = sb + WO_OFF + g * GBUF_SZ;
    const uint32_t wrow = (uint32_t)(ct * 32 + (lane & 15)) * WSTR + (uint32_t)(lane >> 4) * 16
                        + (uint32_t)kh * 32;
    const uint32_t orow = (uint32_t)(lane & 15) * OSTRIDE;

    #pragma unroll 1
    for (int q = 0; q < 16; q++) {
        const int kt = g + ((q >> 1) << 1);
        if (q >= 2) cp_wait<1>();       // uniform commits each iter -> d_{q-2} done
        barx(1 + g);
        const uint32_t ws = WB + (q & 1) * STG_SZ;
        uint32_t Whi0[4], Whi1[4], Wlo0[4], Wlo1[4];
        ldm_x4(Whi0, ws + wrow);
        ldm_x4(Whi1, ws + wrow + 16 * WSTR);
        ldm_x4(Wlo0, ws + 10240 + wrow);
        ldm_x4(Wlo1, ws + 10240 + wrow + 16 * WSTR);
        const uint32_t colb = (uint32_t)(kt * 128 + (q & 1) * 64 + kh * 32);
        const uint32_t xorv = (uint32_t)(((kt * 2 + (q & 1)) & 3) << 4);
        const uint32_t ocol = (colb + (uint32_t)(lane >> 4) * 16) ^ xorv;
        uint32_t OhA[4], OhB[4], OlA[4], OlB[4];
        ldm_x4(OhA, sb + OHI + orow + ocol);
        ldm_x4(OhB, sb + OHI + orow + 16 * OSTRIDE + ocol);
        ldm_x4(OlA, sb + OLO + orow + ocol);
        ldm_x4(OlB, sb + OLO + orow + 16 * OSTRIDE + ocol);
        // whi * Ohi
        mma16816(z[0][0], Whi0, OhA[0], OhA[2]); mma16816(z[0][1], Whi0, OhA[1], OhA[3]);
        mma16816(z[0][2], Whi0, OhB[0], OhB[2]); mma16816(z[0][3], Whi0, OhB[1], OhB[3]);
        mma16816(z[1][0], Whi1, OhA[0], OhA[2]); mma16816(z[1][1], Whi1, OhA[1], OhA[3]);
        mma16816(z[1][2], Whi1, OhB[0], OhB[2]); mma16816(z[1][3], Whi1, OhB[1], OhB[3]);
        // whi * Olo
        mma16816(z[0][0], Whi0, OlA[0], OlA[2]); mma16816(z[0][1], Whi0, OlA[1], OlA[3]);
        mma16816(z[0][2], Whi0, OlB[0], OlB[2]); mma16816(z[0][3], Whi0, OlB[1], OlB[3]);
        mma16816(z[1][0], Whi1, OlA[0], OlA[2]); mma16816(z[1][1], Whi1, OlA[1], OlA[3]);
        mma16816(z[1][2], Whi1, OlB[0], OlB[2]); mma16816(z[1][3], Whi1, OlB[1], OlB[3]);
        // wlo * Ohi
        mma16816(z[0][0], Wlo0, OhA[0], OhA[2]); mma16816(z[0][1], Wlo0, OhA[1], OhA[3]);
        mma16816(z[0][2], Wlo0, OhB[0], OhB[2]); mma16816(z[0][3], Wlo0, OhB[1], OhB[3]);
        mma16816(z[1][0], Wlo1, OhA[0], OhA[2]); mma16816(z[1][1], Wlo1, OhA[1], OhA[3]);
        mma16816(z[1][2], Wlo1, OhB[0], OhB[2]); mma16816(z[1][3], Wlo1, OhB[1], OhB[3]);
        barx(1 + g);
        if (q + 2 < 16) {
            const int q2 = q + 2;
            stage_w(WB + (q & 1) * STG_SZ, g + ((q2 >> 1) << 1), q2 & 1, gt);
        }
        cp_commit();    // uniform group count (maybe empty)
    }

    // ---- 4-stage partial reduction + writeout ----
    __syncthreads();
    float* zs = (float*)(smc + WO_OFF);   // [32p][132cz] floats
    {
        const int mr = lane >> 2, nc = (lane & 3) * 2;
        #pragma unroll 1
        for (int stage = 0; stage < 4; stage++) {
            int sg = 1 - (stage >> 1), skh = 1 - (stage & 1);
            if (g == sg && kh == skh) {
                #pragma unroll
                for (int hf = 0; hf < 2; hf++)
                    #pragma unroll
                    for (int ni = 0; ni < 4; ni++)
                        #pragma unroll
                        for (int e = 0; e < 4; e++) {
                            int cz = ct * 32 + hf * 16 + mr + (e >> 1) * 8;
                            int p  = ni * 8 + nc + (e & 1);
                            if (stage == 0) zs[p * 132 + cz]  = z[hf][ni][e];
                            else            zs[p * 132 + cz] += z[hf][ni][e];
                        }
            }
            __syncthreads();
        }
    }
    #pragma unroll
    for (int q = 0; q < 8; q++) {
        int idx = q * 512 + t;
        int pr = idx >> 7, cz = idx & 127;
        out[((it * 4 + (pr >> 3)) * 512 + jt * 8 + (pr & 7)) * 128 + cz]
            = zs[pr * 132 + cz] + bo[cz];
    }
}

extern "C" void kernel_launch(void* const* d_in, const int* in_sizes, int n_in,
                              void* d_out, int out_size) {
    const float* x  = (const float*)d_in[0];
    const float* nw = (const float*)d_in[1];
    const float* nb = (const float*)d_in[2];
    const float* Wa = (const float*)d_in[3];
    const float* Wb = (const float*)d_in[4];
    const float* Wo = (const float*)d_in[5];
    const float* bo = (const float*)d_in[6];
    float* out = (float*)d_out;

    cudaFuncSetAttribute(ln_proj_kernel, cudaFuncAttributeMaxDynamicSharedMemorySize, K1_SMEM);
    cudaFuncSetAttribute(opm_kernel,     cudaFuncAttributeMaxDynamicSharedMemorySize, SMEM2);

    wo_prep_kernel<<<512, 256>>>(Wo);
    ln_proj_kernel<<<65536 / 16, 256, K1_SMEM>>>(x, nw, nb, Wa, Wb);
    opm_kernel<<<dim3(64, 128), 512, SMEM2>>>(bo, out);
}

// round 10
// speedup vs baseline: 1.5813x; 1.5813x over previous
#include <cuda_runtime.h>
#include <cuda_bf16.h>
#include <cstdint>

// Problem: S=128, I=J=512, CM=256, C=D=32, CZ=128
// opm CTA = 4i x 8j pairs; grid (64 jt, 128 it); 512 threads.
// Phase A: D[128m x 256n], K=384 (bf16 3-term split). 16 warps, tile 32x64.
// Phase B: Z[128cz x 32p], K=16kt x 3terms x 64k; 2 groups (kt parity),
//          round-8 warp mapping (16cz/warp), double-buffered 32-k Wo stages.

// ---------------- smem layout (bytes) ----------------
#define ABUF(b)   ((b) * 55296)
#define BOFF      18432
#define OHI       0
#define OLO       66048
#define OSTRIDE   2064
#define WO_OFF    132096
#define GBUF_SZ   40960     // per group: 2 stages x (hi 10240 + lo 10240)
#define STG_SZ    20480
#define WSTR      80        // Wo stage row stride (64B data + 16 pad)
#define TSTRIDE   144
#define SMEM2     214016
#define K1_SMEM   ((2*32*260 + 16*256) * 4)

// Pre-tiled globals (plain [row][64k] bf16 tiles):
__device__ __align__(256) __nv_bfloat16 g_A3[128 * 6 * 8192];
__device__ __align__(256) __nv_bfloat16 g_B3[64 * 6 * 16384];
__device__ __align__(256) __nv_bfloat16 g_Wo3[32 * 8192];   // kt0-15 hi, 16-31 lo

// ---------------- helpers ----------------
__device__ __forceinline__ uint32_t smem_u32(const void* p) {
    uint32_t a;
    asm("{ .reg .u64 t; cvta.to.shared.u64 t, %1; cvt.u32.u64 %0, t; }" : "=r"(a) : "l"(p));
    return a;
}
__device__ __forceinline__ void cp16(uint32_t smdst, const void* src) {
    asm volatile("cp.async.cg.shared.global [%0], [%1], 16;" :: "r"(smdst), "l"(src));
}
__device__ __forceinline__ void cp_commit() { asm volatile("cp.async.commit_group;"); }
template<int N> __device__ __forceinline__ void cp_wait() {
    asm volatile("cp.async.wait_group %0;" :: "n"(N));
}
__device__ __forceinline__ void barx(int id) {
    asm volatile("bar.sync %0, 256;" :: "r"(id) : "memory");
}
__device__ __forceinline__ void ldm_x4(uint32_t* r, uint32_t addr) {
    asm volatile("ldmatrix.sync.aligned.m8n8.x4.shared.b16 {%0,%1,%2,%3}, [%4];"
                 : "=r"(r[0]), "=r"(r[1]), "=r"(r[2]), "=r"(r[3]) : "r"(addr));
}
__device__ __forceinline__ void mma16816(float* d, const uint32_t* a, uint32_t b0, uint32_t b1) {
    asm volatile(
        "mma.sync.aligned.m16n8k16.row.col.f32.bf16.bf16.f32 "
        "{%0,%1,%2,%3}, {%4,%5,%6,%7}, {%8,%9}, {%0,%1,%2,%3};"
        : "+f"(d[0]), "+f"(d[1]), "+f"(d[2]), "+f"(d[3])
        : "r"(a[0]), "r"(a[1]), "r"(a[2]), "r"(a[3]), "r"(b0), "r"(b1));
}
__device__ __forceinline__ uint32_t packbf(float lo, float hi) {  // lo -> low half
    uint32_t r;
    asm("cvt.rn.satfinite.bf16x2.f32 %0, %1, %2;" : "=r"(r) : "f"(hi), "f"(lo));
    return r;
}
// stage contiguous [rows][64] bf16 tile into smem (TSTRIDE-padded rows)
__device__ __forceinline__ void stage_tile(uint32_t smdst, const __nv_bfloat16* g,
                                           int rows, int t, int nthr) {
    const char* s = (const char*)g;
    for (int idx = t; idx < rows * 8; idx += nthr) {
        int r = idx >> 3, c = idx & 7;
        cp16(smdst + r * TSTRIDE + c * 16, s + r * 128 + c * 16);
    }
}
// stage one 32-k Wo stage (hi+lo halves of tile kt, k-half khalf) with 256 threads
__device__ __forceinline__ void stage_w(uint32_t dst, int kt, int khalf, int gt) {
    const char* hi = (const char*)(g_Wo3 + (size_t)kt * 8192) + khalf * 64;
    const char* lo = (const char*)(g_Wo3 + (size_t)(16 + kt) * 8192) + khalf * 64;
    #pragma unroll
    for (int idx = gt; idx < 512; idx += 256) {
        int r = idx >> 2, c = idx & 3;
        cp16(dst + r * WSTR + c * 16,         hi + r * 128 + c * 16);
        cp16(dst + 10240 + r * WSTR + c * 16, lo + r * 128 + c * 16);
    }
}

// =====================================================================
// Kernel 0: split Wo into hi/lo tiled global.
// =====================================================================
__global__ void wo_prep_kernel(const float* __restrict__ Wo) {
    int idx = blockIdx.x * 256 + threadIdx.x;      // 131072
    int cz = idx >> 10, k = idx & 1023;
    int kt = k >> 6, kk = k & 63;
    float w = Wo[idx];
    __nv_bfloat16 h = __float2bfloat16(w);
    __nv_bfloat16 l = __float2bfloat16(w - __bfloat162float(h));
    g_Wo3[kt * 8192 + cz * 64 + kk]        = h;
    g_Wo3[(16 + kt) * 8192 + cz * 64 + kk] = l;
}

// =====================================================================
// Kernel 1: LayerNorm + dual projection (2 rows per warp -> weight reuse).
// =====================================================================
__global__ __launch_bounds__(256, 2)
void ln_proj_kernel(const float* __restrict__ x,
                    const float* __restrict__ nw,
                    const float* __restrict__ nb,
                    const float* __restrict__ Wa,
                    const float* __restrict__ Wb)
{
    extern __shared__ float sm[];
    float* Wa_s = sm;                 // [32][260]
    float* Wb_s = sm + 32 * 260;
    float* ln_s = sm + 2 * 32 * 260;  // [16][256]

    const int t = threadIdx.x, lane = t & 31, w = t >> 5;

    for (int idx = t; idx < 8192; idx += 256) {
        int c = idx >> 8, m = idx & 255;
        Wa_s[c * 260 + m] = Wa[idx];
        Wb_s[c * 260 + m] = Wb[idx];
    }

    const int r0 = blockIdx.x * 16 + w * 2;
    #pragma unroll
    for (int rr = 0; rr < 2; rr++) {
        const int row = r0 + rr;
        const float* xr = x + (size_t)row * 256;
        float v[8]; float s = 0.f, sq = 0.f;
        #pragma unroll
        for (int h = 0; h < 2; h++) {
            float4 x4 = *(const float4*)(xr + lane * 4 + 128 * h);
            v[h*4+0]=x4.x; v[h*4+1]=x4.y; v[h*4+2]=x4.z; v[h*4+3]=x4.w;
            s  += x4.x + x4.y + x4.z + x4.w;
            sq += x4.x*x4.x + x4.y*x4.y + x4.z*x4.z + x4.w*x4.w;
        }
        #pragma unroll
        for (int o = 16; o > 0; o >>= 1) {
            s  += __shfl_xor_sync(0xffffffffu, s,  o);
            sq += __shfl_xor_sync(0xffffffffu, sq, o);
        }
        float mu  = s * (1.f / 256.f);
        float var = sq * (1.f / 256.f) - mu * mu;
        float rs  = rsqrtf(var + 1e-5f);
        #pragma unroll
        for (int h = 0; h < 2; h++) {
            int m0 = lane * 4 + 128 * h;
            float4 w4 = *(const float4*)(nw + m0);
            float4 b4 = *(const float4*)(nb + m0);
            float* lp = ln_s + (w * 2 + rr) * 256 + m0;
            lp[0] = (v[h*4+0]-mu)*rs*w4.x + b4.x;
            lp[1] = (v[h*4+1]-mu)*rs*w4.y + b4.y;
            lp[2] = (v[h*4+2]-mu)*rs*w4.z + b4.z;
            lp[3] = (v[h*4+3]-mu)*rs*w4.w + b4.w;
        }
    }
    __syncthreads();

    float accA[2] = {0.f, 0.f}, accB[2] = {0.f, 0.f};
    const float* lr0 = ln_s + (w * 2) * 256;
    const float* lr1 = lr0 + 256;
    const float* war = Wa_s + lane * 260;
    const float* wbr = Wb_s + lane * 260;
    #pragma unroll 8
    for (int m4 = 0; m4 < 64; m4++) {
        float4 wa4 = *(const float4*)(war + m4 * 4);
        float4 wb4 = *(const float4*)(wbr + m4 * 4);
        float4 l0  = *(const float4*)(lr0 + m4 * 4);
        float4 l1  = *(const float4*)(lr1 + m4 * 4);
        accA[0] = fmaf(l0.x, wa4.x, accA[0]); accA[0] = fmaf(l0.y, wa4.y, accA[0]);
        accA[0] = fmaf(l0.z, wa4.z, accA[0]); accA[0] = fmaf(l0.w, wa4.w, accA[0]);
        accB[0] = fmaf(l0.x, wb4.x, accB[0]); accB[0] = fmaf(l0.y, wb4.y, accB[0]);
        accB[0] = fmaf(l0.z, wb4.z, accB[0]); accB[0] = fmaf(l0.w, wb4.w, accB[0]);
        accA[1] = fmaf(l1.x, wa4.x, accA[1]); accA[1] = fmaf(l1.y, wa4.y, accA[1]);
        accA[1] = fmaf(l1.z, wa4.z, accA[1]); accA[1] = fmaf(l1.w, wa4.w, accA[1]);
        accB[1] = fmaf(l1.x, wb4.x, accB[1]); accB[1] = fmaf(l1.y, wb4.y, accB[1]);
        accB[1] = fmaf(l1.z, wb4.z, accB[1]); accB[1] = fmaf(l1.w, wb4.w, accB[1]);
    }

    #pragma unroll
    for (int rr = 0; rr < 2; rr++) {
        const int row = r0 + rr;
        __nv_bfloat16 ah = __float2bfloat16(accA[rr]);
        __nv_bfloat16 al = __float2bfloat16(accA[rr] - __bfloat162float(ah));
        __nv_bfloat16 bh = __float2bfloat16(accB[rr]);
        __nv_bfloat16 bl = __float2bfloat16(accB[rr] - __bfloat162float(bh));
        const int ss = row >> 9, ij = row & 511;
        const int kts = ss >> 6, kk = ss & 63;
        {   // A terms: kt = kts(ahi), 2+kts(ahi), 4+kts(alo)
            int it = ij >> 2, m = (ij & 3) * 32 + lane;
            __nv_bfloat16* base = g_A3 + (size_t)(it * 6) * 8192 + m * 64 + kk;
            base[(size_t)kts * 8192]       = ah;
            base[(size_t)(2 + kts) * 8192] = ah;
            base[(size_t)(4 + kts) * 8192] = al;
        }
        {   // B terms: bhi, blo, bhi
            int jt = ij >> 3, n = (ij & 7) * 32 + lane;
            __nv_bfloat16* base = g_B3 + (size_t)(jt * 6) * 16384 + n * 64 + kk;
            base[(size_t)kts * 16384]       = bh;
            base[(size_t)(2 + kts) * 16384] = bl;
            base[(size_t)(4 + kts) * 16384] = bh;
        }
    }
}

// =====================================================================
// Kernel 2: fused OPM + projection, 512 threads.
// =====================================================================
__global__ __launch_bounds__(512, 1)
void opm_kernel(const float* __restrict__ bo, float* __restrict__ out)
{
    extern __shared__ char smc[];
    const uint32_t sb = smem_u32(smc);
    const int t = threadIdx.x, lane = t & 31, wid = t >> 5;
    const int jt = blockIdx.x, it = blockIdx.y;
    const int g  = wid >> 3;              // phase-B group (kt parity)
    const int gt = t & 255;

    const __nv_bfloat16* Abase = g_A3 + (size_t)(it * 6) * 8192;
    const __nv_bfloat16* Bbase = g_B3 + (size_t)(jt * 6) * 16384;

    // ---- prologue. Per-thread commits: c0=AB0 c1=AB1 c2=Wstage0 c3=Wstage1 ----
    stage_tile(sb + ABUF(0),        Abase,         128, t, 512);
    stage_tile(sb + ABUF(0) + BOFF, Bbase,         256, t, 512);
    cp_commit();                                                    // c0
    stage_tile(sb + ABUF(1),        Abase + 8192,  128, t, 512);
    stage_tile(sb + ABUF(1) + BOFF, Bbase + 16384, 256, t, 512);
    cp_commit();                                                    // c1
    {   // group g: stage q=0 (kt=g, k0-31), stage q=1 (kt=g, k32-63)
        uint32_t WB = sb + WO_OFF + g * GBUF_SZ;
        stage_w(WB,          g, 0, gt);  cp_commit();               // c2
        stage_w(WB + STG_SZ, g, 1, gt);  cp_commit();               // c3
    }

    // ---- Phase A: 16 warps, 4x4 grid of 32m x 64n tiles ----
    const int wm = wid & 3, wn = wid >> 2;
    const uint32_t lrow = (uint32_t)(lane & 15) * TSTRIDE;
    const uint32_t lcol = (uint32_t)(lane >> 4) * 16;
    float acc[2][8][4];
    #pragma unroll
    for (int mt = 0; mt < 2; mt++)
        #pragma unroll
        for (int nt = 0; nt < 8; nt++)
            #pragma unroll
            for (int e = 0; e < 4; e++) acc[mt][nt][e] = 0.f;

    #pragma unroll 1
    for (int kt = 0; kt < 6; kt++) {
        // commits audited: kt<2: wait<3>; 2..4: wait<1>; 5: wait<0>
        if (kt < 2) cp_wait<3>(); else if (kt < 5) cp_wait<1>(); else cp_wait<0>();
        __syncthreads();
        const uint32_t ab = sb + ABUF(kt & 1);
        const uint32_t aB = ab + (uint32_t)(wm * 32) * TSTRIDE + lrow + lcol;
        const uint32_t bB = ab + BOFF + (uint32_t)(wn * 64) * TSTRIDE + lrow + lcol;
        #pragma unroll
        for (int k16 = 0; k16 < 4; k16++) {
            uint32_t A4[2][4], B4[4][4];
            #pragma unroll
            for (int mt = 0; mt < 2; mt++) ldm_x4(A4[mt], aB + mt * 16 * TSTRIDE + k16 * 32);
            #pragma unroll
            for (int bt = 0; bt < 4; bt++) ldm_x4(B4[bt], bB + bt * 16 * TSTRIDE + k16 * 32);
            #pragma unroll
            for (int mt = 0; mt < 2; mt++)
                #pragma unroll
                for (int bt = 0; bt < 4; bt++) {
                    mma16816(acc[mt][bt*2],   A4[mt], B4[bt][0], B4[bt][2]);
                    mma16816(acc[mt][bt*2+1], A4[mt], B4[bt][1], B4[bt][3]);
                }
        }
        __syncthreads();
        if (kt < 4) {
            stage_tile(sb + ABUF(kt & 1),        Abase + (size_t)(kt+2) * 8192,  128, t, 512);
            stage_tile(sb + ABUF(kt & 1) + BOFF, Bbase + (size_t)(kt+2) * 16384, 256, t, 512);
            cp_commit();                                            // c4..c7
        }
    }

    // ---- Epilogue: accums -> O hi/lo smem (round-8 layout) ----
    {
        const int m0 = wm * 32, n0 = wn * 64;
        const int mr = lane >> 2, nc = (lane & 3) * 2;
        #pragma unroll
        for (int mt = 0; mt < 2; mt++)
            #pragma unroll
            for (int nt = 0; nt < 8; nt++) {
                #pragma unroll
                for (int h = 0; h < 2; h++) {
                    int m = m0 + mt * 16 + mr + h * 8;
                    int n = n0 + nt * 8 + nc;
                    float f0 = acc[mt][nt][2*h]   * (1.f / 128.f);
                    float f1 = acc[mt][nt][2*h+1] * (1.f / 128.f);
                    float h0 = __bfloat162float(__float2bfloat16(f0));
                    float h1 = __bfloat162float(__float2bfloat16(f1));
                    uint32_t hi = packbf(f0, f1);
                    uint32_t lo = packbf(f0 - h0, f1 - h1);
                    int p = (m >> 5) * 8 + (n >> 5);
                    int k = (m & 31) * 32 + (n & 31);
                    uint32_t off = (uint32_t)(p * OSTRIDE + k * 2);
                    asm volatile("st.shared.b32 [%0], %1;" :: "r"(sb + OHI + off), "r"(hi) : "memory");
                    asm volatile("st.shared.b32 [%0], %1;" :: "r"(sb + OLO + off), "r"(lo) : "memory");
                }
            }
    }
    __syncthreads();

    // ---- Phase B: group g, stage q covers kt = g+2*(q>>1), k-half = q&1 ----
    float z[4][4];
    #pragma unroll
    for (int nt = 0; nt < 4; nt++)
        #pragma unroll
        for (int e = 0; e < 4; e++) z[nt][e] = 0.f;

    const int wg  = wid & 7;
    const int czt = wg * 16;
    const uint32_t WB   = sb + WO_OFF + g * GBUF_SZ;
    const uint32_t wrow = (uint32_t)(czt + (lane & 15)) * WSTR + (uint32_t)(lane >> 4) * 16;
    const uint32_t orow = (uint32_t)(lane & 15) * OSTRIDE + (uint32_t)(lane >> 4) * 16;

    #pragma unroll 1
    for (int q = 0; q < 16; q++) {
        const int kt = g + ((q >> 1) << 1);
        const int kh = q & 1;
        if (q >= 2) cp_wait<1>();       // uniform commits: stage for q landed
        barx(1 + g);
        const uint32_t ws = WB + (q & 1) * STG_SZ;
        #pragma unroll
        for (int k16 = 0; k16 < 2; k16++) {
            uint32_t Whi[4], Wlo[4], OhA[4], OhB[4], OlA[4], OlB[4];
            ldm_x4(Whi, ws + wrow + k16 * 32);
            ldm_x4(Wlo, ws + 10240 + wrow + k16 * 32);
            const uint32_t ob = sb + OHI + orow
                              + (uint32_t)(kt * 128 + kh * 64 + k16 * 32);
            ldm_x4(OhA, ob);
            ldm_x4(OhB, ob + 16 * OSTRIDE);
            ldm_x4(OlA, ob + (OLO - OHI));
            ldm_x4(OlB, ob + (OLO - OHI) + 16 * OSTRIDE);
            // whi*Ohi
            mma16816(z[0], Whi, OhA[0], OhA[2]); mma16816(z[1], Whi, OhA[1], OhA[3]);
            mma16816(z[2], Whi, OhB[0], OhB[2]); mma16816(z[3], Whi, OhB[1], OhB[3]);
            // whi*Olo
            mma16816(z[0], Whi, OlA[0], OlA[2]); mma16816(z[1], Whi, OlA[1], OlA[3]);
            mma16816(z[2], Whi, OlB[0], OlB[2]); mma16816(z[3], Whi, OlB[1], OlB[3]);
            // wlo*Ohi
            mma16816(z[0], Wlo, OhA[0], OhA[2]); mma16816(z[1], Wlo, OhA[1], OhA[3]);
            mma16816(z[2], Wlo, OhB[0], OhB[2]); mma16816(z[3], Wlo, OhB[1], OhB[3]);
        }
        barx(1 + g);
        if (q + 2 < 16) {
            const int q2 = q + 2;
            stage_w(WB + (q & 1) * STG_SZ, g + ((q2 >> 1) << 1), q2 & 1, gt);
        }
        cp_commit();    // uniform group count (maybe empty)
    }

    // ---- reduce group partials + writeout (round-8 scheme) ----
    __syncthreads();
    float* zs = (float*)(smc + WO_OFF);   // [32][132] floats (reuses group-0 buf)
    {
        const int mr = lane >> 2, nc = (lane & 3) * 2;
        if (g == 1) {
            #pragma unroll
            for (int nt = 0; nt < 4; nt++)
                #pragma unroll
                for (int e = 0; e < 4; e++) {
                    int cz = czt + mr + (e >> 1) * 8;
                    int pr = nt * 8 + nc + (e & 1);
                    zs[pr * 132 + cz] = z[nt][e];
                }
        }
        __syncthreads();
        if (g == 0) {
            #pragma unroll
            for (int nt = 0; nt < 4; nt++)
                #pragma unroll
                for (int e = 0; e < 4; e++) {
                    int cz = czt + mr + (e >> 1) * 8;
                    int pr = nt * 8 + nc + (e & 1);
                    zs[pr * 132 + cz] += z[nt][e];
                }
        }
    }
    __syncthreads();
    #pragma unroll
    for (int q = 0; q < 8; q++) {
        int idx = q * 512 + t;
        int pr = idx >> 7, cz = idx & 127;
        out[((it * 4 + (pr >> 3)) * 512 + jt * 8 + (pr & 7)) * 128 + cz]
            = zs[pr * 132 + cz] + bo[cz];
    }
}

extern "C" void kernel_launch(void* const* d_in, const int* in_sizes, int n_in,
                              void* d_out, int out_size) {
    const float* x  = (const float*)d_in[0];
    const float* nw = (const float*)d_in[1];
    const float* nb = (const float*)d_in[2];
    const float* Wa = (const float*)d_in[3];
    const float* Wb = (const float*)d_in[4];
    const float* Wo = (const float*)d_in[5];
    const float* bo = (const float*)d_in[6];
    float* out = (float*)d_out;

    cudaFuncSetAttribute(ln_proj_kernel, cudaFuncAttributeMaxDynamicSharedMemorySize, K1_SMEM);
    cudaFuncSetAttribute(opm_kernel,     cudaFuncAttributeMaxDynamicSharedMemorySize, SMEM2);

    wo_prep_kernel<<<512, 256>>>(Wo);
    ln_proj_kernel<<<65536 / 16, 256, K1_SMEM>>>(x, nw, nb, Wa, Wb);
    opm_kernel<<<dim3(64, 128), 512, SMEM2>>>(bo, out);
}

// round 11
// speedup vs baseline: 2.3920x; 1.5127x over previous
#include <cuda_runtime.h>
#include <cuda_fp16.h>
#include <cstdint>

// Problem: S=128, I=J=512, CM=256, C=D=32, CZ=128
// opm CTA = 4i x 8j pairs; grid (64 jt, 128 it); 512 threads. fp16 2-product split.
// Phase A: D[128m x 256n], K=256 ([Ah|Ah] x [Bh|Bl]). 16 warps, tile 32x64.
// Phase B: Z[128cz x 32p], K=16kt x 2prod x 64k (Wh·Oh + Wh·Ol); hi-only Wo stream.

// ---------------- smem layout (bytes) ----------------
#define A_RES     0          // 2 resident A tiles: [128][72] fp16 x2 = 36864
#define B_BUF(b)  (36864 + (b) * 36864)   // 2 x [256][72] fp16
#define OHI       0          // O hi [32p][1032k] fp16 (overlaps phase-A bufs; sequential)
#define OLO       66048
#define OSTRIDE   2064
#define WO_OFF    132096
#define GBUF_SZ   20480      // per group: 2 stages x 10240 (hi only)
#define STG_SZ    10240
#define WSTR      80         // Wo stage row stride (64B data + 16 pad)
#define TSTRIDE   144
#define SMEM2     173056
#define K1_SMEM   ((2*32*260 + 16*256) * 4)

// Pre-tiled globals (plain [row][64k] fp16 tiles):
// g_A3: per it: 2 tiles (Ah s0-63, Ah s64-127) of [128m][64k]
// g_B3: per jt: 4 tiles (Bh0, Bh1, Bl0, Bl1) of [256n][64k]
// g_Wo3: 16 hi tiles [128cz][64k]
__device__ __align__(256) __half g_A3[128 * 2 * 8192];
__device__ __align__(256) __half g_B3[64 * 4 * 16384];
__device__ __align__(256) __half g_Wo3[16 * 8192];

// ---------------- helpers ----------------
__device__ __forceinline__ uint32_t smem_u32(const void* p) {
    uint32_t a;
    asm("{ .reg .u64 t; cvta.to.shared.u64 t, %1; cvt.u32.u64 %0, t; }" : "=r"(a) : "l"(p));
    return a;
}
__device__ __forceinline__ void cp16(uint32_t smdst, const void* src) {
    asm volatile("cp.async.cg.shared.global [%0], [%1], 16;" :: "r"(smdst), "l"(src));
}
__device__ __forceinline__ void cp_commit() { asm volatile("cp.async.commit_group;"); }
template<int N> __device__ __forceinline__ void cp_wait() {
    asm volatile("cp.async.wait_group %0;" :: "n"(N));
}
__device__ __forceinline__ void barx(int id) {
    asm volatile("bar.sync %0, 256;" :: "r"(id) : "memory");
}
__device__ __forceinline__ void ldm_x4(uint32_t* r, uint32_t addr) {
    asm volatile("ldmatrix.sync.aligned.m8n8.x4.shared.b16 {%0,%1,%2,%3}, [%4];"
                 : "=r"(r[0]), "=r"(r[1]), "=r"(r[2]), "=r"(r[3]) : "r"(addr));
}
__device__ __forceinline__ void mma16816(float* d, const uint32_t* a, uint32_t b0, uint32_t b1) {
    asm volatile(
        "mma.sync.aligned.m16n8k16.row.col.f32.f16.f16.f32 "
        "{%0,%1,%2,%3}, {%4,%5,%6,%7}, {%8,%9}, {%0,%1,%2,%3};"
        : "+f"(d[0]), "+f"(d[1]), "+f"(d[2]), "+f"(d[3])
        : "r"(a[0]), "r"(a[1]), "r"(a[2]), "r"(a[3]), "r"(b0), "r"(b1));
}
__device__ __forceinline__ uint32_t packh2(float lo, float hi) {  // lo -> low half
    __half2 h = __floats2half2_rn(lo, hi);
    return *(uint32_t*)&h;
}
// O column swizzle: col in [0,2048) bytes; bijective, identical on store & load.
__device__ __forceinline__ uint32_t oswz(uint32_t col) {
    return col ^ (((col >> 6) & 7u) << 4);
}
// stage contiguous [rows][64] fp16 tile into smem (TSTRIDE-padded rows)
__device__ __forceinline__ void stage_tile(uint32_t smdst, const __half* g,
                                           int rows, int t, int nthr) {
    const char* s = (const char*)g;
    for (int idx = t; idx < rows * 8; idx += nthr) {
        int r = idx >> 3, c = idx & 7;
        cp16(smdst + r * TSTRIDE + c * 16, s + r * 128 + c * 16);
    }
}
// stage one 32-k hi Wo stage (tile kt, k-half khalf) with 256 threads
__device__ __forceinline__ void stage_w(uint32_t dst, int kt, int khalf, int gt) {
    const char* hi = (const char*)(g_Wo3 + (size_t)kt * 8192) + khalf * 64;
    #pragma unroll
    for (int idx = gt; idx < 512; idx += 256) {
        int r = idx >> 2, c = idx & 3;
        cp16(dst + r * WSTR + c * 16, hi + r * 128 + c * 16);
    }
}

// =====================================================================
// Kernel 0: Wo -> fp16 hi tiled global.
// =====================================================================
__global__ void wo_prep_kernel(const float* __restrict__ Wo) {
    int idx = blockIdx.x * 256 + threadIdx.x;      // 131072
    int cz = idx >> 10, k = idx & 1023;
    int kt = k >> 6, kk = k & 63;
    g_Wo3[kt * 8192 + cz * 64 + kk] = __float2half_rn(Wo[idx]);
}

// =====================================================================
// Kernel 1: LayerNorm + dual projection -> fp16 pre-tiled globals.
// =====================================================================
__global__ __launch_bounds__(256, 2)
void ln_proj_kernel(const float* __restrict__ x,
                    const float* __restrict__ nw,
                    const float* __restrict__ nb,
                    const float* __restrict__ Wa,
                    const float* __restrict__ Wb)
{
    extern __shared__ float sm[];
    float* Wa_s = sm;                 // [32][260]
    float* Wb_s = sm + 32 * 260;
    float* ln_s = sm + 2 * 32 * 260;  // [16][256]

    const int t = threadIdx.x, lane = t & 31, w = t >> 5;

    for (int idx = t; idx < 8192; idx += 256) {
        int c = idx >> 8, m = idx & 255;
        Wa_s[c * 260 + m] = Wa[idx];
        Wb_s[c * 260 + m] = Wb[idx];
    }

    const int r0 = blockIdx.x * 16 + w * 2;
    #pragma unroll
    for (int rr = 0; rr < 2; rr++) {
        const int row = r0 + rr;
        const float* xr = x + (size_t)row * 256;
        float v[8]; float s = 0.f, sq = 0.f;
        #pragma unroll
        for (int h = 0; h < 2; h++) {
            float4 x4 = *(const float4*)(xr + lane * 4 + 128 * h);
            v[h*4+0]=x4.x; v[h*4+1]=x4.y; v[h*4+2]=x4.z; v[h*4+3]=x4.w;
            s  += x4.x + x4.y + x4.z + x4.w;
            sq += x4.x*x4.x + x4.y*x4.y + x4.z*x4.z + x4.w*x4.w;
        }
        #pragma unroll
        for (int o = 16; o > 0; o >>= 1) {
            s  += __shfl_xor_sync(0xffffffffu, s,  o);
            sq += __shfl_xor_sync(0xffffffffu, sq, o);
        }
        float mu  = s * (1.f / 256.f);
        float var = sq * (1.f / 256.f) - mu * mu;
        float rs  = rsqrtf(var + 1e-5f);
        #pragma unroll
        for (int h = 0; h < 2; h++) {
            int m0 = lane * 4 + 128 * h;
            float4 w4 = *(const float4*)(nw + m0);
            float4 b4 = *(const float4*)(nb + m0);
            float* lp = ln_s + (w * 2 + rr) * 256 + m0;
            lp[0] = (v[h*4+0]-mu)*rs*w4.x + b4.x;
            lp[1] = (v[h*4+1]-mu)*rs*w4.y + b4.y;
            lp[2] = (v[h*4+2]-mu)*rs*w4.z + b4.z;
            lp[3] = (v[h*4+3]-mu)*rs*w4.w + b4.w;
        }
    }
    __syncthreads();

    float accA[2] = {0.f, 0.f}, accB[2] = {0.f, 0.f};
    const float* lr0 = ln_s + (w * 2) * 256;
    const float* lr1 = lr0 + 256;
    const float* war = Wa_s + lane * 260;
    const float* wbr = Wb_s + lane * 260;
    #pragma unroll 8
    for (int m4 = 0; m4 < 64; m4++) {
        float4 wa4 = *(const float4*)(war + m4 * 4);
        float4 wb4 = *(const float4*)(wbr + m4 * 4);
        float4 l0  = *(const float4*)(lr0 + m4 * 4);
        float4 l1  = *(const float4*)(lr1 + m4 * 4);
        accA[0] = fmaf(l0.x, wa4.x, accA[0]); accA[0] = fmaf(l0.y, wa4.y, accA[0]);
        accA[0] = fmaf(l0.z, wa4.z, accA[0]); accA[0] = fmaf(l0.w, wa4.w, accA[0]);
        accB[0] = fmaf(l0.x, wb4.x, accB[0]); accB[0] = fmaf(l0.y, wb4.y, accB[0]);
        accB[0] = fmaf(l0.z, wb4.z, accB[0]); accB[0] = fmaf(l0.w, wb4.w, accB[0]);
        accA[1] = fmaf(l1.x, wa4.x, accA[1]); accA[1] = fmaf(l1.y, wa4.y, accA[1]);
        accA[1] = fmaf(l1.z, wa4.z, accA[1]); accA[1] = fmaf(l1.w, wa4.w, accA[1]);
        accB[1] = fmaf(l1.x, wb4.x, accB[1]); accB[1] = fmaf(l1.y, wb4.y, accB[1]);
        accB[1] = fmaf(l1.z, wb4.z, accB[1]); accB[1] = fmaf(l1.w, wb4.w, accB[1]);
    }

    #pragma unroll
    for (int rr = 0; rr < 2; rr++) {
        const int row = r0 + rr;
        __half ah = __float2half_rn(accA[rr]);
        __half bh = __float2half_rn(accB[rr]);
        __half bl = __float2half_rn(accB[rr] - __half2float(bh));
        const int ss = row >> 9, ij = row & 511;
        const int kts = ss >> 6, kk = ss & 63;
        {   // A: only Ah at tile kts
            int it = ij >> 2, m = (ij & 3) * 32 + lane;
            g_A3[(size_t)(it * 2 + kts) * 8192 + m * 64 + kk] = ah;
        }
        {   // B: Bh at tile kts, Bl at tile 2+kts
            int jt = ij >> 3, n = (ij & 7) * 32 + lane;
            __half* base = g_B3 + (size_t)(jt * 4) * 16384 + n * 64 + kk;
            base[(size_t)kts * 16384]       = bh;
            base[(size_t)(2 + kts) * 16384] = bl;
        }
    }
}

// =====================================================================
// Kernel 2: fused OPM + projection, 512 threads, fp16 2-product.
// =====================================================================
__global__ __launch_bounds__(512, 1)
void opm_kernel(const float* __restrict__ bo, float* __restrict__ out)
{
    extern __shared__ char smc[];
    const uint32_t sb = smem_u32(smc);
    const int t = threadIdx.x, lane = t & 31, wid = t >> 5;
    const int jt = blockIdx.x, it = blockIdx.y;
    const int g  = wid >> 3;              // phase-B group (kt parity)
    const int gt = t & 255;

    const __half* Abase = g_A3 + (size_t)(it * 2) * 8192;
    const __half* Bbase = g_B3 + (size_t)(jt * 4) * 16384;

    // ---- prologue. Commits: c0={A0,A1,B0} c1={B1} c2=Wst0 c3=Wst1 ----
    stage_tile(sb + A_RES,         Abase,         128, t, 512);
    stage_tile(sb + A_RES + 18432, Abase + 8192,  128, t, 512);
    stage_tile(sb + B_BUF(0),      Bbase,         256, t, 512);
    cp_commit();                                                    // c0
    stage_tile(sb + B_BUF(1),      Bbase + 16384, 256, t, 512);
    cp_commit();                                                    // c1
    {   // group g: stage q=0 (kt=g, k0-31), q=1 (kt=g, k32-63)
        uint32_t WB = sb + WO_OFF + g * GBUF_SZ;
        stage_w(WB,          g, 0, gt);  cp_commit();               // c2
        stage_w(WB + STG_SZ, g, 1, gt);  cp_commit();               // c3
    }

    // ---- Phase A: kt 0..3 -> B tiles [Bh0,Bh1,Bl0,Bl1], A tile = kt&1 ----
    const int wm = wid & 3, wn = wid >> 2;
    const uint32_t lrow = (uint32_t)(lane & 15) * TSTRIDE;
    const uint32_t lcol = (uint32_t)(lane >> 4) * 16;
    float acc[2][8][4];
    #pragma unroll
    for (int mt = 0; mt < 2; mt++)
        #pragma unroll
        for (int nt = 0; nt < 8; nt++)
            #pragma unroll
            for (int e = 0; e < 4; e++) acc[mt][nt][e] = 0.f;

    #pragma unroll 1
    for (int kt = 0; kt < 4; kt++) {
        // waits audited: kt0,1: wait<3>; kt2: wait<1>; kt3: wait<0>
        if (kt < 2) cp_wait<3>(); else if (kt < 3) cp_wait<1>(); else cp_wait<0>();
        __syncthreads();
        const uint32_t aB = sb + A_RES + (uint32_t)(kt & 1) * 18432
                          + (uint32_t)(wm * 32) * TSTRIDE + lrow + lcol;
        const uint32_t bB = sb + B_BUF(kt & 1)
                          + (uint32_t)(wn * 64) * TSTRIDE + lrow + lcol;
        #pragma unroll
        for (int k16 = 0; k16 < 4; k16++) {
            uint32_t A4[2][4], B4[4][4];
            #pragma unroll
            for (int mt = 0; mt < 2; mt++) ldm_x4(A4[mt], aB + mt * 16 * TSTRIDE + k16 * 32);
            #pragma unroll
            for (int bt = 0; bt < 4; bt++) ldm_x4(B4[bt], bB + bt * 16 * TSTRIDE + k16 * 32);
            #pragma unroll
            for (int mt = 0; mt < 2; mt++)
                #pragma unroll
                for (int bt = 0; bt < 4; bt++) {
                    mma16816(acc[mt][bt*2],   A4[mt], B4[bt][0], B4[bt][2]);
                    mma16816(acc[mt][bt*2+1], A4[mt], B4[bt][1], B4[bt][3]);
                }
        }
        __syncthreads();
        if (kt < 2) {
            stage_tile(sb + B_BUF(kt & 1), Bbase + (size_t)(kt + 2) * 16384, 256, t, 512);
        }
        cp_commit();                                                // c4,c5,c6,c7
    }

    // ---- Epilogue: accums -> O hi/lo smem (fp16 split, XOR-swizzled cols) ----
    {
        const int m0 = wm * 32, n0 = wn * 64;
        const int mr = lane >> 2, nc = (lane & 3) * 2;
        #pragma unroll
        for (int mt = 0; mt < 2; mt++)
            #pragma unroll
            for (int nt = 0; nt < 8; nt++) {
                #pragma unroll
                for (int h = 0; h < 2; h++) {
                    int m = m0 + mt * 16 + mr + h * 8;
                    int n = n0 + nt * 8 + nc;
                    float f0 = acc[mt][nt][2*h]   * (1.f / 128.f);
                    float f1 = acc[mt][nt][2*h+1] * (1.f / 128.f);
                    __half h0 = __float2half_rn(f0);
                    __half h1 = __float2half_rn(f1);
                    uint32_t hi = packh2(f0, f1);
                    uint32_t lo = packh2(f0 - __half2float(h0), f1 - __half2float(h1));
                    int p = (m >> 5) * 8 + (n >> 5);
                    uint32_t col = oswz((uint32_t)(((m & 31) * 32 + (n & 31)) * 2));
                    uint32_t off = (uint32_t)(p * OSTRIDE) + col;
                    asm volatile("st.shared.b32 [%0], %1;" :: "r"(sb + OHI + off), "r"(hi) : "memory");
                    asm volatile("st.shared.b32 [%0], %1;" :: "r"(sb + OLO + off), "r"(lo) : "memory");
                }
            }
    }
    __syncthreads();

    // ---- Phase B: group g, stage q: kt = g+2*(q>>1), k-half = q&1 ----
    float z[4][4];
    #pragma unroll
    for (int nt = 0; nt < 4; nt++)
        #pragma unroll
        for (int e = 0; e < 4; e++) z[nt][e] = 0.f;

    const int wg  = wid & 7;
    const int czt = wg * 16;
    const uint32_t WB   = sb + WO_OFF + g * GBUF_SZ;
    const uint32_t wrow = (uint32_t)(czt + (lane & 15)) * WSTR + (uint32_t)(lane >> 4) * 16;
    const uint32_t orow = (uint32_t)(lane & 15) * OSTRIDE;

    #pragma unroll 1
    for (int q = 0; q < 16; q++) {
        const int kt = g + ((q >> 1) << 1);
        const int kh = q & 1;
        cp_wait<1>();       // uniform commits: stage for q landed
        barx(1 + g);
        const uint32_t ws = WB + (q & 1) * STG_SZ;
        #pragma unroll
        for (int k16 = 0; k16 < 2; k16++) {
            uint32_t Whi[4], OhA[4], OhB[4], OlA[4], OlB[4];
            ldm_x4(Whi, ws + wrow + k16 * 32);
            const uint32_t ocol = oswz((uint32_t)(kt * 128 + kh * 64 + k16 * 32)
                                       + (uint32_t)(lane >> 4) * 16);
            const uint32_t ob = sb + OHI + orow + ocol;
            ldm_x4(OhA, ob);
            ldm_x4(OhB, ob + 16 * OSTRIDE);
            ldm_x4(OlA, ob + (OLO - OHI));
            ldm_x4(OlB, ob + (OLO - OHI) + 16 * OSTRIDE);
            // Wh*Oh
            mma16816(z[0], Whi, OhA[0], OhA[2]); mma16816(z[1], Whi, OhA[1], OhA[3]);
            mma16816(z[2], Whi, OhB[0], OhB[2]); mma16816(z[3], Whi, OhB[1], OhB[3]);
            // Wh*Ol
            mma16816(z[0], Whi, OlA[0], OlA[2]); mma16816(z[1], Whi, OlA[1], OlA[3]);
            mma16816(z[2], Whi, OlB[0], OlB[2]); mma16816(z[3], Whi, OlB[1], OlB[3]);
        }
        barx(1 + g);
        if (q + 2 < 16) {
            const int q2 = q + 2;
            stage_w(WB + (q & 1) * STG_SZ, g + ((q2 >> 1) << 1), q2 & 1, gt);
        }
        cp_commit();    // uniform group count (maybe empty)
    }

    // ---- reduce group partials + writeout ----
    __syncthreads();
    float* zs = (float*)(smc + WO_OFF);   // [32][132] floats (reuses Wo region)
    {
        const int mr = lane >> 2, nc = (lane & 3) * 2;
        if (g == 1) {
            #pragma unroll
            for (int nt = 0; nt < 4; nt++)
                #pragma unroll
                for (int e = 0; e < 4; e++) {
                    int cz = czt + mr + (e >> 1) * 8;
                    int pr = nt * 8 + nc + (e & 1);
                    zs[pr * 132 + cz] = z[nt][e];
                }
        }
        __syncthreads();
        if (g == 0) {
            #pragma unroll
            for (int nt = 0; nt < 4; nt++)
                #pragma unroll
                for (int e = 0; e < 4; e++) {
                    int cz = czt + mr + (e >> 1) * 8;
                    int pr = nt * 8 + nc + (e & 1);
                    zs[pr * 132 + cz] += z[nt][e];
                }
        }
    }
    __syncthreads();
    #pragma unroll
    for (int q = 0; q < 8; q++) {
        int idx = q * 512 + t;
        int pr = idx >> 7, cz = idx & 127;
        out[((it * 4 + (pr >> 3)) * 512 + jt * 8 + (pr & 7)) * 128 + cz]
            = zs[pr * 132 + cz] + bo[cz];
    }
}

extern "C" void kernel_launch(void* const* d_in, const int* in_sizes, int n_in,
                              void* d_out, int out_size) {
    const float* x  = (const float*)d_in[0];
    const float* nw = (const float*)d_in[1];
    const float* nb = (const float*)d_in[2];
    const float* Wa = (const float*)d_in[3];
    const float* Wb = (const float*)d_in[4];
    const float* Wo = (const float*)d_in[5];
    const float* bo = (const float*)d_in[6];
    float* out = (float*)d_out;

    cudaFuncSetAttribute(ln_proj_kernel, cudaFuncAttributeMaxDynamicSharedMemorySize, K1_SMEM);
    cudaFuncSetAttribute(opm_kernel,     cudaFuncAttributeMaxDynamicSharedMemorySize, SMEM2);

    wo_prep_kernel<<<512, 256>>>(Wo);
    ln_proj_kernel<<<65536 / 16, 256, K1_SMEM>>>(x, nw, nb, Wa, Wb);
    opm_kernel<<<dim3(64, 128), 512, SMEM2>>>(bo, out);
}

// round 12
// speedup vs baseline: 3.4497x; 1.4422x over previous
#include <cuda_runtime.h>
#include <cuda_fp16.h>
#include <cstdint>

// Problem: S=128, I=J=512, CM=256, C=D=32, CZ=128
// opm CTA = 4i x 8j pairs; grid (64 jt, 128 it); 512 threads. Pure fp16.
// Phase A: D[128m x 256n], K=128 (Ah·Bh). 16 warps, tile 32x64.
// Phase B: Z[128cz x 32p], K=16kt x 64k (Wh·Oh); hi-only Wo stream.

// ---------------- smem layout (bytes) ----------------
#define A_RES     0          // 2 resident A tiles: [128][72] fp16 x2 = 36864
#define B_BUF(b)  (36864 + (b) * 36864)   // 2 x [256][72] fp16  (ends 110592)
#define OHI       0          // O hi [32p][1032k] fp16 (overlaps phase-A bufs; sequential)
#define OSTRIDE   2064
#define WO_OFF    110592
#define GBUF_SZ   20480      // per group: 2 stages x 10240 (hi only)
#define STG_SZ    10240
#define WSTR      80         // Wo stage row stride (64B data + 16 pad)
#define TSTRIDE   144
#define SMEM2     151552
#define K1_SMEM   ((2*32*260 + 16*256) * 4)

// Pre-tiled globals (plain [row][64k] fp16 tiles):
// g_A3: per it: 2 tiles (Ah s0-63, Ah s64-127) of [128m][64k]
// g_B3: per jt: 2 tiles (Bh s0-63, Bh s64-127) of [256n][64k]
// g_Wo3: 16 hi tiles [128cz][64k]
__device__ __align__(256) __half g_A3[128 * 2 * 8192];
__device__ __align__(256) __half g_B3[64 * 2 * 16384];
__device__ __align__(256) __half g_Wo3[16 * 8192];

// ---------------- helpers ----------------
__device__ __forceinline__ uint32_t smem_u32(const void* p) {
    uint32_t a;
    asm("{ .reg .u64 t; cvta.to.shared.u64 t, %1; cvt.u32.u64 %0, t; }" : "=r"(a) : "l"(p));
    return a;
}
__device__ __forceinline__ void cp16(uint32_t smdst, const void* src) {
    asm volatile("cp.async.cg.shared.global [%0], [%1], 16;" :: "r"(smdst), "l"(src));
}
__device__ __forceinline__ void cp_commit() { asm volatile("cp.async.commit_group;"); }
template<int N> __device__ __forceinline__ void cp_wait() {
    asm volatile("cp.async.wait_group %0;" :: "n"(N));
}
__device__ __forceinline__ void barx(int id) {
    asm volatile("bar.sync %0, 256;" :: "r"(id) : "memory");
}
__device__ __forceinline__ void ldm_x4(uint32_t* r, uint32_t addr) {
    asm volatile("ldmatrix.sync.aligned.m8n8.x4.shared.b16 {%0,%1,%2,%3}, [%4];"
                 : "=r"(r[0]), "=r"(r[1]), "=r"(r[2]), "=r"(r[3]) : "r"(addr));
}
__device__ __forceinline__ void mma16816(float* d, const uint32_t* a, uint32_t b0, uint32_t b1) {
    asm volatile(
        "mma.sync.aligned.m16n8k16.row.col.f32.f16.f16.f32 "
        "{%0,%1,%2,%3}, {%4,%5,%6,%7}, {%8,%9}, {%0,%1,%2,%3};"
        : "+f"(d[0]), "+f"(d[1]), "+f"(d[2]), "+f"(d[3])
        : "r"(a[0]), "r"(a[1]), "r"(a[2]), "r"(a[3]), "r"(b0), "r"(b1));
}
__device__ __forceinline__ uint32_t packh2(float lo, float hi) {  // lo -> low half
    __half2 h = __floats2half2_rn(lo, hi);
    return *(uint32_t*)&h;
}
// O column swizzle: col in [0,2048) bytes; bijective, identical on store & load.
__device__ __forceinline__ uint32_t oswz(uint32_t col) {
    return col ^ (((col >> 6) & 7u) << 4);
}
// stage contiguous [rows][64] fp16 tile into smem (TSTRIDE-padded rows)
__device__ __forceinline__ void stage_tile(uint32_t smdst, const __half* g,
                                           int rows, int t, int nthr) {
    const char* s = (const char*)g;
    for (int idx = t; idx < rows * 8; idx += nthr) {
        int r = idx >> 3, c = idx & 7;
        cp16(smdst + r * TSTRIDE + c * 16, s + r * 128 + c * 16);
    }
}
// stage one 32-k hi Wo stage (tile kt, k-half khalf) with 256 threads
__device__ __forceinline__ void stage_w(uint32_t dst, int kt, int khalf, int gt) {
    const char* hi = (const char*)(g_Wo3 + (size_t)kt * 8192) + khalf * 64;
    #pragma unroll
    for (int idx = gt; idx < 512; idx += 256) {
        int r = idx >> 2, c = idx & 3;
        cp16(dst + r * WSTR + c * 16, hi + r * 128 + c * 16);
    }
}

// =====================================================================
// Kernel 0: Wo -> fp16 hi tiled global.
// =====================================================================
__global__ void wo_prep_kernel(const float* __restrict__ Wo) {
    int idx = blockIdx.x * 256 + threadIdx.x;      // 131072
    int cz = idx >> 10, k = idx & 1023;
    int kt = k >> 6, kk = k & 63;
    g_Wo3[kt * 8192 + cz * 64 + kk] = __float2half_rn(Wo[idx]);
}

// =====================================================================
// Kernel 1: LayerNorm + dual projection -> fp16 pre-tiled globals.
// =====================================================================
__global__ __launch_bounds__(256, 2)
void ln_proj_kernel(const float* __restrict__ x,
                    const float* __restrict__ nw,
                    const float* __restrict__ nb,
                    const float* __restrict__ Wa,
                    const float* __restrict__ Wb)
{
    extern __shared__ float sm[];
    float* Wa_s = sm;                 // [32][260]
    float* Wb_s = sm + 32 * 260;
    float* ln_s = sm + 2 * 32 * 260;  // [16][256]

    const int t = threadIdx.x, lane = t & 31, w = t >> 5;

    for (int idx = t; idx < 8192; idx += 256) {
        int c = idx >> 8, m = idx & 255;
        Wa_s[c * 260 + m] = Wa[idx];
        Wb_s[c * 260 + m] = Wb[idx];
    }

    const int r0 = blockIdx.x * 16 + w * 2;
    #pragma unroll
    for (int rr = 0; rr < 2; rr++) {
        const int row = r0 + rr;
        const float* xr = x + (size_t)row * 256;
        float v[8]; float s = 0.f, sq = 0.f;
        #pragma unroll
        for (int h = 0; h < 2; h++) {
            float4 x4 = *(const float4*)(xr + lane * 4 + 128 * h);
            v[h*4+0]=x4.x; v[h*4+1]=x4.y; v[h*4+2]=x4.z; v[h*4+3]=x4.w;
            s  += x4.x + x4.y + x4.z + x4.w;
            sq += x4.x*x4.x + x4.y*x4.y + x4.z*x4.z + x4.w*x4.w;
        }
        #pragma unroll
        for (int o = 16; o > 0; o >>= 1) {
            s  += __shfl_xor_sync(0xffffffffu, s,  o);
            sq += __shfl_xor_sync(0xffffffffu, sq, o);
        }
        float mu  = s * (1.f / 256.f);
        float var = sq * (1.f / 256.f) - mu * mu;
        float rs  = rsqrtf(var + 1e-5f);
        #pragma unroll
        for (int h = 0; h < 2; h++) {
            int m0 = lane * 4 + 128 * h;
            float4 w4 = *(const float4*)(nw + m0);
            float4 b4 = *(const float4*)(nb + m0);
            float* lp = ln_s + (w * 2 + rr) * 256 + m0;
            lp[0] = (v[h*4+0]-mu)*rs*w4.x + b4.x;
            lp[1] = (v[h*4+1]-mu)*rs*w4.y + b4.y;
            lp[2] = (v[h*4+2]-mu)*rs*w4.z + b4.z;
            lp[3] = (v[h*4+3]-mu)*rs*w4.w + b4.w;
        }
    }
    __syncthreads();

    float accA[2] = {0.f, 0.f}, accB[2] = {0.f, 0.f};
    const float* lr0 = ln_s + (w * 2) * 256;
    const float* lr1 = lr0 + 256;
    const float* war = Wa_s + lane * 260;
    const float* wbr = Wb_s + lane * 260;
    #pragma unroll 8
    for (int m4 = 0; m4 < 64; m4++) {
        float4 wa4 = *(const float4*)(war + m4 * 4);
        float4 wb4 = *(const float4*)(wbr + m4 * 4);
        float4 l0  = *(const float4*)(lr0 + m4 * 4);
        float4 l1  = *(const float4*)(lr1 + m4 * 4);
        accA[0] = fmaf(l0.x, wa4.x, accA[0]); accA[0] = fmaf(l0.y, wa4.y, accA[0]);
        accA[0] = fmaf(l0.z, wa4.z, accA[0]); accA[0] = fmaf(l0.w, wa4.w, accA[0]);
        accB[0] = fmaf(l0.x, wb4.x, accB[0]); accB[0] = fmaf(l0.y, wb4.y, accB[0]);
        accB[0] = fmaf(l0.z, wb4.z, accB[0]); accB[0] = fmaf(l0.w, wb4.w, accB[0]);
        accA[1] = fmaf(l1.x, wa4.x, accA[1]); accA[1] = fmaf(l1.y, wa4.y, accA[1]);
        accA[1] = fmaf(l1.z, wa4.z, accA[1]); accA[1] = fmaf(l1.w, wa4.w, accA[1]);
        accB[1] = fmaf(l1.x, wb4.x, accB[1]); accB[1] = fmaf(l1.y, wb4.y, accB[1]);
        accB[1] = fmaf(l1.z, wb4.z, accB[1]); accB[1] = fmaf(l1.w, wb4.w, accB[1]);
    }

    #pragma unroll
    for (int rr = 0; rr < 2; rr++) {
        const int row = r0 + rr;
        __half ah = __float2half_rn(accA[rr]);
        __half bh = __float2half_rn(accB[rr]);
        const int ss = row >> 9, ij = row & 511;
        const int kts = ss >> 6, kk = ss & 63;
        {   // A: Ah at tile kts
            int it = ij >> 2, m = (ij & 3) * 32 + lane;
            g_A3[(size_t)(it * 2 + kts) * 8192 + m * 64 + kk] = ah;
        }
        {   // B: Bh at tile kts
            int jt = ij >> 3, n = (ij & 7) * 32 + lane;
            g_B3[(size_t)(jt * 2 + kts) * 16384 + n * 64 + kk] = bh;
        }
    }
}

// =====================================================================
// Kernel 2: fused OPM + projection, 512 threads, pure fp16.
// =====================================================================
__global__ __launch_bounds__(512, 1)
void opm_kernel(const float* __restrict__ bo, float* __restrict__ out)
{
    extern __shared__ char smc[];
    const uint32_t sb = smem_u32(smc);
    const int t = threadIdx.x, lane = t & 31, wid = t >> 5;
    const int jt = blockIdx.x, it = blockIdx.y;
    const int g  = wid >> 3;              // phase-B group (kt parity)
    const int gt = t & 255;

    const __half* Abase = g_A3 + (size_t)(it * 2) * 8192;
    const __half* Bbase = g_B3 + (size_t)(jt * 2) * 16384;

    // ---- prologue. Commits: c0={A0,A1,B0} c1={B1} c2=Wst0 c3=Wst1 ----
    stage_tile(sb + A_RES,         Abase,         128, t, 512);
    stage_tile(sb + A_RES + 18432, Abase + 8192,  128, t, 512);
    stage_tile(sb + B_BUF(0),      Bbase,         256, t, 512);
    cp_commit();                                                    // c0
    stage_tile(sb + B_BUF(1),      Bbase + 16384, 256, t, 512);
    cp_commit();                                                    // c1
    {   // group g: stage q=0 (kt=g, k0-31), q=1 (kt=g, k32-63)
        uint32_t WB = sb + WO_OFF + g * GBUF_SZ;
        stage_w(WB,          g, 0, gt);  cp_commit();               // c2
        stage_w(WB + STG_SZ, g, 1, gt);  cp_commit();               // c3
    }

    // ---- Phase A: kt 0..1, A tile kt, B tile kt ----
    const int wm = wid & 3, wn = wid >> 2;
    const uint32_t lrow = (uint32_t)(lane & 15) * TSTRIDE;
    const uint32_t lcol = (uint32_t)(lane >> 4) * 16;
    float acc[2][8][4];
    #pragma unroll
    for (int mt = 0; mt < 2; mt++)
        #pragma unroll
        for (int nt = 0; nt < 8; nt++)
            #pragma unroll
            for (int e = 0; e < 4; e++) acc[mt][nt][e] = 0.f;

    #pragma unroll 1
    for (int kt = 0; kt < 2; kt++) {
        // waits audited: kt0: wait<3> (c0 done); kt1: wait<2> (c1 done)
        if (kt == 0) cp_wait<3>(); else cp_wait<2>();
        __syncthreads();
        const uint32_t aB = sb + A_RES + (uint32_t)kt * 18432
                          + (uint32_t)(wm * 32) * TSTRIDE + lrow + lcol;
        const uint32_t bB = sb + B_BUF(kt)
                          + (uint32_t)(wn * 64) * TSTRIDE + lrow + lcol;
        #pragma unroll
        for (int k16 = 0; k16 < 4; k16++) {
            uint32_t A4[2][4], B4[4][4];
            #pragma unroll
            for (int mt = 0; mt < 2; mt++) ldm_x4(A4[mt], aB + mt * 16 * TSTRIDE + k16 * 32);
            #pragma unroll
            for (int bt = 0; bt < 4; bt++) ldm_x4(B4[bt], bB + bt * 16 * TSTRIDE + k16 * 32);
            #pragma unroll
            for (int mt = 0; mt < 2; mt++)
                #pragma unroll
                for (int bt = 0; bt < 4; bt++) {
                    mma16816(acc[mt][bt*2],   A4[mt], B4[bt][0], B4[bt][2]);
                    mma16816(acc[mt][bt*2+1], A4[mt], B4[bt][1], B4[bt][3]);
                }
        }
        __syncthreads();
    }

    // ---- Epilogue: accums -> O hi smem (fp16, XOR-swizzled cols) ----
    {
        const int m0 = wm * 32, n0 = wn * 64;
        const int mr = lane >> 2, nc = (lane & 3) * 2;
        #pragma unroll
        for (int mt = 0; mt < 2; mt++)
            #pragma unroll
            for (int nt = 0; nt < 8; nt++) {
                #pragma unroll
                for (int h = 0; h < 2; h++) {
                    int m = m0 + mt * 16 + mr + h * 8;
                    int n = n0 + nt * 8 + nc;
                    float f0 = acc[mt][nt][2*h]   * (1.f / 128.f);
                    float f1 = acc[mt][nt][2*h+1] * (1.f / 128.f);
                    uint32_t hi = packh2(f0, f1);
                    int p = (m >> 5) * 8 + (n >> 5);
                    uint32_t col = oswz((uint32_t)(((m & 31) * 32 + (n & 31)) * 2));
                    uint32_t off = (uint32_t)(p * OSTRIDE) + col;
                    asm volatile("st.shared.b32 [%0], %1;" :: "r"(sb + OHI + off), "r"(hi) : "memory");
                }
            }
    }
    __syncthreads();

    // ---- Phase B: group g, stage q: kt = g+2*(q>>1), k-half = q&1 ----
    float z[4][4];
    #pragma unroll
    for (int nt = 0; nt < 4; nt++)
        #pragma unroll
        for (int e = 0; e < 4; e++) z[nt][e] = 0.f;

    const int wg  = wid & 7;
    const int czt = wg * 16;
    const uint32_t WB   = sb + WO_OFF + g * GBUF_SZ;
    const uint32_t wrow = (uint32_t)(czt + (lane & 15)) * WSTR + (uint32_t)(lane >> 4) * 16;
    const uint32_t orow = (uint32_t)(lane & 15) * OSTRIDE;

    #pragma unroll 1
    for (int q = 0; q < 16; q++) {
        const int kt = g + ((q >> 1) << 1);
        const int kh = q & 1;
        cp_wait<1>();       // uniform commits: stage for q landed
        barx(1 + g);
        const uint32_t ws = WB + (q & 1) * STG_SZ;
        #pragma unroll
        for (int k16 = 0; k16 < 2; k16++) {
            uint32_t Whi[4], OhA[4], OhB[4];
            ldm_x4(Whi, ws + wrow + k16 * 32);
            const uint32_t ocol = oswz((uint32_t)(kt * 128 + kh * 64 + k16 * 32)
                                       + (uint32_t)(lane >> 4) * 16);
            const uint32_t ob = sb + OHI + orow + ocol;
            ldm_x4(OhA, ob);
            ldm_x4(OhB, ob + 16 * OSTRIDE);
            mma16816(z[0], Whi, OhA[0], OhA[2]); mma16816(z[1], Whi, OhA[1], OhA[3]);
            mma16816(z[2], Whi, OhB[0], OhB[2]); mma16816(z[3], Whi, OhB[1], OhB[3]);
        }
        barx(1 + g);
        if (q + 2 < 16) {
            const int q2 = q + 2;
            stage_w(WB + (q & 1) * STG_SZ, g + ((q2 >> 1) << 1), q2 & 1, gt);
        }
        cp_commit();    // uniform group count (maybe empty)
    }

    // ---- reduce group partials + writeout ----
    __syncthreads();
    float* zs = (float*)(smc + WO_OFF);   // [32][132] floats (reuses Wo region)
    {
        const int mr = lane >> 2, nc = (lane & 3) * 2;
        if (g == 1) {
            #pragma unroll
            for (int nt = 0; nt < 4; nt++)
                #pragma unroll
                for (int e = 0; e < 4; e++) {
                    int cz = czt + mr + (e >> 1) * 8;
                    int pr = nt * 8 + nc + (e & 1);
                    zs[pr * 132 + cz] = z[nt][e];
                }
        }
        __syncthreads();
        if (g == 0) {
            #pragma unroll
            for (int nt = 0; nt < 4; nt++)
                #pragma unroll
                for (int e = 0; e < 4; e++) {
                    int cz = czt + mr + (e >> 1) * 8;
                    int pr = nt * 8 + nc + (e & 1);
                    zs[pr * 132 + cz] += z[nt][e];
                }
        }
    }
    __syncthreads();
    #pragma unroll
    for (int q = 0; q < 8; q++) {
        int idx = q * 512 + t;
        int pr = idx >> 7, cz = idx & 127;
        out[((it * 4 + (pr >> 3)) * 512 + jt * 8 + (pr & 7)) * 128 + cz]
            = zs[pr * 132 + cz] + bo[cz];
    }
}

extern "C" void kernel_launch(void* const* d_in, const int* in_sizes, int n_in,
                              void* d_out, int out_size) {
    const float* x  = (const float*)d_in[0];
    const float* nw = (const float*)d_in[1];
    const float* nb = (const float*)d_in[2];
    const float* Wa = (const float*)d_in[3];
    const float* Wb = (const float*)d_in[4];
    const float* Wo = (const float*)d_in[5];
    const float* bo = (const float*)d_in[6];
    float* out = (float*)d_out;

    cudaFuncSetAttribute(ln_proj_kernel, cudaFuncAttributeMaxDynamicSharedMemorySize, K1_SMEM);
    cudaFuncSetAttribute(opm_kernel,     cudaFuncAttributeMaxDynamicSharedMemorySize, SMEM2);

    wo_prep_kernel<<<512, 256>>>(Wo);
    ln_proj_kernel<<<65536 / 16, 256, K1_SMEM>>>(x, nw, nb, Wa, Wb);
    opm_kernel<<<dim3(64, 128), 512, SMEM2>>>(bo, out);
}